// round 9
// baseline (speedup 1.0000x reference)
#include <cuda_runtime.h>
#include <cuda_bf16.h>
#include <cstdint>

// Problem constants
#define BATCH 8
#define NQ    2048
#define NS    4096
#define DIM   512

// Tiling (int8: BK = 128 int8 per chunk, 4 ksteps of K=32)
#define BM 128
#define BN 128
#define BK 128
#define NCHUNK ((NS / BN) * (DIM / BK))   // 32 stiles * 4 kchunks = 128
#define NBUF 3
#define NTHREADS 256

#define A_BYTES    (BM * DIM)             // 65536 = 4 chunks of 16KB (128 int8 cols)
#define BBUF_BYTES (BN * BK)              // 16384
#define SS_OFF     (A_BYTES + NBUF * BBUF_BYTES)   // 114688 (s-scale table, 16KB)
#define RM_OFF     (SS_OFF + NS * 4)               // 131072
#define SMEM_TOTAL (RM_OFF + BM * 4)               // 131584

// Device scratch
__device__ __align__(16) int8_t g_q8[(size_t)BATCH * NQ * DIM];
__device__ __align__(16) int8_t g_s8[(size_t)BATCH * NS * DIM];
__device__ float g_qsc[(size_t)BATCH * NQ];   // amax_y/127 per query row
__device__ float g_ssc[(size_t)BATCH * NS];   // amax_y/127 per support row

// ---------------------------------------------------------------------------
// helpers
// ---------------------------------------------------------------------------
__device__ __forceinline__ uint32_t swz(uint32_t x) {   // SW128: bits[6:4] ^= bits[9:7]
    return x ^ ((x >> 3) & 0x70);
}
__device__ __forceinline__ void cp_async16(uint32_t saddr, const void* gptr) {
    asm volatile("cp.async.cg.shared.global [%0], [%1], 16;\n" :: "r"(saddr), "l"(gptr));
}
__device__ __forceinline__ void cp_commit() {
    asm volatile("cp.async.commit_group;\n" ::: "memory");
}
template <int N>
__device__ __forceinline__ void cp_wait() {
    asm volatile("cp.async.wait_group %0;\n" :: "n"(N) : "memory");
}
__device__ __forceinline__ unsigned fkey(float f) {
    unsigned u = __float_as_uint(f);
    return (u & 0x80000000u) ? ~u : (u | 0x80000000u);
}
__device__ __forceinline__ float funkey(unsigned k) {
    unsigned u = (k & 0x80000000u) ? (k ^ 0x80000000u) : ~k;
    return __uint_as_float(u);
}

// ---------------------------------------------------------------------------
// Normalize + int8 quantize: one warp per row. Lane owns 16 consecutive elems.
// y = x / max(||x||,eps);  q8 = rint(y * 127/amax(|y|));  scale = amax/127.
// ---------------------------------------------------------------------------
__device__ __forceinline__ void normalize_row_q(const float* __restrict__ rinF,
                                                int8_t* __restrict__ orow,
                                                float* __restrict__ oscale, int lane)
{
    const float4* rin = reinterpret_cast<const float4*>(rinF);
    float4 v[4];
    float s = 0.f, am = 0.f;
#pragma unroll
    for (int j = 0; j < 4; j++) {
        v[j] = rin[lane * 4 + j];
        s += v[j].x * v[j].x + v[j].y * v[j].y + v[j].z * v[j].z + v[j].w * v[j].w;
        am = fmaxf(am, fmaxf(fmaxf(fabsf(v[j].x), fabsf(v[j].y)),
                             fmaxf(fabsf(v[j].z), fabsf(v[j].w))));
    }
#pragma unroll
    for (int o = 16; o > 0; o >>= 1) {
        s  += __shfl_xor_sync(0xFFFFFFFFu, s, o);
        am  = fmaxf(am, __shfl_xor_sync(0xFFFFFFFFu, am, o));
    }
    float inv = 1.0f / fmaxf(sqrtf(s), 1e-12f);
    float amax_y = fmaxf(am * inv, 1e-30f);
    float f = inv * (127.0f / amax_y);

    unsigned p[4];
#pragma unroll
    for (int j = 0; j < 4; j++) {
        int a = min(127, max(-127, __float2int_rn(v[j].x * f)));
        int bq = min(127, max(-127, __float2int_rn(v[j].y * f)));
        int c = min(127, max(-127, __float2int_rn(v[j].z * f)));
        int d = min(127, max(-127, __float2int_rn(v[j].w * f)));
        p[j] = (unsigned)(a & 0xFF) | ((unsigned)(bq & 0xFF) << 8)
             | ((unsigned)(c & 0xFF) << 16) | ((unsigned)(d & 0xFF) << 24);
    }
    uint4 pk = make_uint4(p[0], p[1], p[2], p[3]);
    reinterpret_cast<uint4*>(orow)[lane] = pk;
    if (lane == 0) *oscale = amax_y * (1.0f / 127.0f);
}

__global__ void normalize_all_kernel(const float* __restrict__ q,
                                     const float* __restrict__ s,
                                     float* __restrict__ out)
{
    if (blockIdx.x == 0 && threadIdx.x < BATCH) out[threadIdx.x] = 0.f;
    int row = blockIdx.x * (blockDim.x >> 5) + (threadIdx.x >> 5);
    int lane = threadIdx.x & 31;
    const int nq = BATCH * NQ;
    const int ntot = nq + BATCH * NS;
    if (row >= ntot) return;
    if (row < nq)
        normalize_row_q(q + (size_t)row * DIM, g_q8 + (size_t)row * DIM,
                        &g_qsc[row], lane);
    else {
        int r = row - nq;
        normalize_row_q(s + (size_t)r * DIM, g_s8 + (size_t)r * DIM,
                        &g_ssc[r], lane);
    }
}

// ---------------------------------------------------------------------------
// B chunk fill: chunk ci covers support rows [st*128,+128), int8 k-cols
// [kc*128,+128). 1024 x 16B segments, 4 per thread (256 threads).
// ---------------------------------------------------------------------------
__device__ __forceinline__ void fill_b_chunk(uint32_t smem_u32,
                                             const int8_t* __restrict__ gB,
                                             int ci, int tid)
{
    const int st = ci >> 2;
    const int kc = ci & 3;
    const uint32_t bb = A_BYTES + (uint32_t)(ci % NBUF) * BBUF_BYTES;
#pragma unroll
    for (int i = 0; i < 4; i++) {
        int idx = tid + i * NTHREADS;    // 0..1023
        int r = idx >> 3;                // 8 segs per 128B row
        int s8 = idx & 7;
        const void* src = gB + (size_t)(st * BN + r) * DIM + kc * BK + s8 * 16;
        cp_async16(smem_u32 + bb + swz((uint32_t)(r * 128 + s8 * 16)), src);
    }
    cp_commit();
}

// ---------------------------------------------------------------------------
// GEMM-max (int8): one block per (batch, q-tile). 256 threads, 8 warps
// (2m x 4n), warp tile 64x32. A resident, B 3-buffer depth-2 cp.async
// pipeline. mma.sync m16n8k32 s8 -> s32. Row-max folded in fp32 with
// per-support-row scales; query scale applied after max (monotone).
// ---------------------------------------------------------------------------
__global__ __launch_bounds__(NTHREADS, 1) void gemm_max_kernel(float* __restrict__ out)
{
    extern __shared__ char smem[];
    float* ssm = reinterpret_cast<float*>(smem + SS_OFF);
    unsigned* rowmaxU = reinterpret_cast<unsigned*>(smem + RM_OFF);
    __shared__ float red[NTHREADS / 32];
    const uint32_t smem_u32 = (uint32_t)__cvta_generic_to_shared(smem);

    const int b   = blockIdx.x >> 4;
    const int qt  = blockIdx.x & 15;
    const int tid = threadIdx.x;
    const int lane = tid & 31;
    const int wid  = tid >> 5;
    const int wm = (wid >> 2) * 64;
    const int wn = (wid & 3) * 32;

    if (tid < BM) rowmaxU[tid] = 0u;

    // ---- A tile: 128 x 512 int8, 4 swizzled 128B-wide chunks ----
    const int8_t* gA = g_q8 + (size_t)(b * NQ + qt * BM) * DIM;
#pragma unroll
    for (int i = 0; i < 16; i++) {
        int idx = tid + i * NTHREADS;    // 0..4095 16B segs
        int r = idx >> 5;                // 32 segs per row
        int rest = idx & 31;
        int ch = rest >> 3;
        int s8 = rest & 7;
        const void* src = gA + (size_t)r * DIM + ch * BK + s8 * 16;
        cp_async16(smem_u32 + ch * 16384 + swz((uint32_t)(r * 128 + s8 * 16)), src);
    }
    cp_commit();

    const int8_t* gB = g_s8 + (size_t)b * NS * DIM;

    // prologue: chunks 0, 1
    fill_b_chunk(smem_u32, gB, 0, tid);
    fill_b_chunk(smem_u32, gB, 1, tid);

    // s-scale table for this batch: 4096 floats (plain loads; visible after
    // the first chunk's __syncthreads)
    {
        const float4* gss = reinterpret_cast<const float4*>(g_ssc + (size_t)b * NS);
        float4* dss = reinterpret_cast<float4*>(ssm);
#pragma unroll
        for (int i = 0; i < 4; i++) dss[tid + i * NTHREADS] = gss[tid + i * NTHREADS];
    }

    int C[4][4][4];
#pragma unroll
    for (int mi = 0; mi < 4; mi++)
#pragma unroll
        for (int ni = 0; ni < 4; ni++)
#pragma unroll
            for (int e = 0; e < 4; e++) C[mi][ni][e] = 0;

    float rmax[4][2];
#pragma unroll
    for (int mi = 0; mi < 4; mi++) { rmax[mi][0] = -1e30f; rmax[mi][1] = -1e30f; }

    for (int ci = 0; ci < NCHUNK; ci++) {
        if (ci < NCHUNK - 1) cp_wait<1>(); else cp_wait<0>();
        __syncthreads();
        if (ci + 2 < NCHUNK) fill_b_chunk(smem_u32, gB, ci + 2, tid);

        const int kc = ci & 3;
        const int st = ci >> 2;
        const uint32_t bb = A_BYTES + (uint32_t)(ci % NBUF) * BBUF_BYTES;

#pragma unroll
        for (int ksp = 0; ksp < 2; ksp++) {
            // B x4: 2 ksteps (64B of k) per instruction, 4 n-tiles
            unsigned bfr[4][4];
            {
                const uint32_t kb = (uint32_t)(ksp * 64
                                  + ((lane >> 3) & 1) * 16 + (lane >> 4) * 32);
#pragma unroll
                for (int ni = 0; ni < 4; ni++) {
                    int n = wn + ni * 8 + (lane & 7);
                    uint32_t addr = smem_u32 + bb + swz((uint32_t)(n * 128) + kb);
                    asm volatile("ldmatrix.sync.aligned.m8n8.x4.shared.b16 {%0,%1,%2,%3}, [%4];"
                                 : "=r"(bfr[ni][0]), "=r"(bfr[ni][1]),
                                   "=r"(bfr[ni][2]), "=r"(bfr[ni][3])
                                 : "r"(addr));
                }
            }
#pragma unroll
            for (int h = 0; h < 2; h++) {
                const int ks = ksp * 2 + h;
                const uint32_t kb = (uint32_t)(ks * 32 + (lane >> 4) * 16);
                unsigned af[4][4];
#pragma unroll
                for (int mi = 0; mi < 4; mi++) {
                    int r0 = wm + mi * 16 + (lane & 15);
                    uint32_t addr = smem_u32 + kc * 16384
                                  + swz((uint32_t)(r0 * 128) + kb);
                    asm volatile("ldmatrix.sync.aligned.m8n8.x4.shared.b16 {%0,%1,%2,%3}, [%4];"
                                 : "=r"(af[mi][0]), "=r"(af[mi][1]),
                                   "=r"(af[mi][2]), "=r"(af[mi][3])
                                 : "r"(addr));
                }
#pragma unroll
                for (int mi = 0; mi < 4; mi++)
#pragma unroll
                    for (int ni = 0; ni < 4; ni++) {
                        asm volatile(
                            "mma.sync.aligned.m16n8k32.row.col.s32.s8.s8.s32 "
                            "{%0,%1,%2,%3}, {%4,%5,%6,%7}, {%8,%9}, {%0,%1,%2,%3};"
                            : "+r"(C[mi][ni][0]), "+r"(C[mi][ni][1]),
                              "+r"(C[mi][ni][2]), "+r"(C[mi][ni][3])
                            : "r"(af[mi][0]), "r"(af[mi][1]),
                              "r"(af[mi][2]), "r"(af[mi][3]),
                              "r"(bfr[ni][2 * h]), "r"(bfr[ni][2 * h + 1]));
                    }
            }
        }

        if (kc == 3) {   // end of s-tile: scale by support-row scales, fold max
            const int cbase = st * 128 + wn + (lane & 3) * 2;
#pragma unroll
            for (int ni = 0; ni < 4; ni++) {
                const float s0 = ssm[cbase + ni * 8];
                const float s1 = ssm[cbase + ni * 8 + 1];
#pragma unroll
                for (int mi = 0; mi < 4; mi++) {
                    rmax[mi][0] = fmaxf(rmax[mi][0],
                                        fmaxf((float)C[mi][ni][0] * s0,
                                              (float)C[mi][ni][1] * s1));
                    rmax[mi][1] = fmaxf(rmax[mi][1],
                                        fmaxf((float)C[mi][ni][2] * s0,
                                              (float)C[mi][ni][3] * s1));
                    C[mi][ni][0] = 0; C[mi][ni][1] = 0;
                    C[mi][ni][2] = 0; C[mi][ni][3] = 0;
                }
            }
        }
    }

    // epilogue: apply query-row scale (monotone per row), combine via smem atomics
    const float* qsc = g_qsc + (size_t)b * NQ + qt * BM;
#pragma unroll
    for (int t = 0; t < 4; t++) {
#pragma unroll
        for (int g = 0; g < 2; g++) {
            int row = wm + t * 16 + (lane >> 2) + g * 8;
            atomicMax(&rowmaxU[row], fkey(rmax[t][g] * qsc[row]));
        }
    }
    __syncthreads();

    // fused finalize: block sum of (1 - rowmax) -> atomicAdd(out[b], sum/NQ)
    float v = 0.f;
    if (tid < BM) v = 1.0f - funkey(rowmaxU[tid]);
#pragma unroll
    for (int o = 16; o > 0; o >>= 1) v += __shfl_xor_sync(0xFFFFFFFFu, v, o);
    if (lane == 0) red[wid] = v;
    __syncthreads();
    if (wid == 0) {
        float sum = (lane < NTHREADS / 32) ? red[lane] : 0.f;
#pragma unroll
        for (int o = 4; o > 0; o >>= 1) sum += __shfl_xor_sync(0xFFFFFFFFu, sum, o);
        if (lane == 0) atomicAdd(&out[b], sum * (1.0f / NQ));
    }
}

// ---------------------------------------------------------------------------
extern "C" void kernel_launch(void* const* d_in, const int* in_sizes, int n_in,
                              void* d_out, int out_size)
{
    const float* q = (const float*)d_in[0];
    const float* s = (const float*)d_in[1];
    float* out = (float*)d_out;

    cudaFuncSetAttribute(gemm_max_kernel,
                         cudaFuncAttributeMaxDynamicSharedMemorySize, SMEM_TOTAL);

    const int nrows = BATCH * (NQ + NS);
    normalize_all_kernel<<<(nrows + 7) / 8, 256>>>(q, s, out);
    gemm_max_kernel<<<BATCH * (NQ / BM), NTHREADS, SMEM_TOTAL>>>(out);
}

// round 10
// speedup vs baseline: 2.8398x; 2.8398x over previous
#include <cuda_runtime.h>
#include <cuda_bf16.h>
#include <cstdint>

// Problem constants
#define BATCH 8
#define NQ    2048
#define NS    4096
#define DIM   512

// Tiling: two independent 256-thread groups per CTA, each BM=128 x BN=128,
// BK=64 chunks, own 3-buffer ring, own named barrier. Group g handles
// s-tiles g, g+2, ... (16 each), 8 k-chunks per s-tile -> 128 chunks/group.
#define BM 128
#define BN 128
#define BK 64
#define GCHUNK 128
#define NBUF 3
#define NTHREADS 512

#define A_BYTES    (BM * DIM * 2)              // 131072 = 8 chunks of 16KB
#define BBUF_BYTES (BN * BK * 2)               // 16384
#define RM_OFF     (A_BYTES + 2 * NBUF * BBUF_BYTES)   // 229376
#define SMEM_TOTAL (RM_OFF + BM * 4)                   // 229888

// Device scratch
__device__ __nv_bfloat16 g_qn[(size_t)BATCH * NQ * DIM];
__device__ __nv_bfloat16 g_sn[(size_t)BATCH * NS * DIM];

// ---------------------------------------------------------------------------
// helpers
// ---------------------------------------------------------------------------
__device__ __forceinline__ uint32_t swz(uint32_t x) {   // SW128: bits[6:4] ^= bits[9:7]
    return x ^ ((x >> 3) & 0x70);
}
__device__ __forceinline__ void cp_async16(uint32_t saddr, const void* gptr) {
    asm volatile("cp.async.cg.shared.global [%0], [%1], 16;\n" :: "r"(saddr), "l"(gptr));
}
__device__ __forceinline__ void cp_commit() {
    asm volatile("cp.async.commit_group;\n" ::: "memory");
}
template <int N>
__device__ __forceinline__ void cp_wait() {
    asm volatile("cp.async.wait_group %0;\n" :: "n"(N) : "memory");
}
__device__ __forceinline__ void bar_g(int id) {
    asm volatile("bar.sync %0, 256;" :: "r"(id) : "memory");
}
__device__ __forceinline__ unsigned fkey(float f) {
    unsigned u = __float_as_uint(f);
    return (u & 0x80000000u) ? ~u : (u | 0x80000000u);
}
__device__ __forceinline__ float funkey(unsigned k) {
    unsigned u = (k & 0x80000000u) ? (k ^ 0x80000000u) : ~k;
    return __uint_as_float(u);
}

// ---------------------------------------------------------------------------
// Normalize: one warp per row of 512 fp32 -> bf16. Also zeroes out[].
// ---------------------------------------------------------------------------
__device__ __forceinline__ void normalize_row(const float* __restrict__ rinF,
                                              __nv_bfloat16* __restrict__ orow, int lane)
{
    const float4* rin = reinterpret_cast<const float4*>(rinF);
    float4 v[4];
    float s = 0.f;
#pragma unroll
    for (int j = 0; j < 4; j++) {
        v[j] = rin[j * 32 + lane];
        s += v[j].x * v[j].x + v[j].y * v[j].y + v[j].z * v[j].z + v[j].w * v[j].w;
    }
#pragma unroll
    for (int o = 16; o > 0; o >>= 1) s += __shfl_xor_sync(0xFFFFFFFFu, s, o);
    float inv = 1.0f / fmaxf(sqrtf(s), 1e-12f);
#pragma unroll
    for (int j = 0; j < 4; j++) {
        __nv_bfloat162 h0 = __floats2bfloat162_rn(v[j].x * inv, v[j].y * inv);
        __nv_bfloat162 h1 = __floats2bfloat162_rn(v[j].z * inv, v[j].w * inv);
        uint2 pk;
        pk.x = *reinterpret_cast<unsigned*>(&h0);
        pk.y = *reinterpret_cast<unsigned*>(&h1);
        *reinterpret_cast<uint2*>(orow + (size_t)(j * 32 + lane) * 4) = pk;
    }
}

__global__ void normalize_all_kernel(const float* __restrict__ q,
                                     const float* __restrict__ s,
                                     float* __restrict__ out)
{
    if (blockIdx.x == 0 && threadIdx.x < BATCH) out[threadIdx.x] = 0.f;
    int row = blockIdx.x * (blockDim.x >> 5) + (threadIdx.x >> 5);
    int lane = threadIdx.x & 31;
    const int nq = BATCH * NQ;
    const int ntot = nq + BATCH * NS;
    if (row >= ntot) return;
    if (row < nq)
        normalize_row(q + (size_t)row * DIM, g_qn + (size_t)row * DIM, lane);
    else {
        int r = row - nq;
        normalize_row(s + (size_t)r * DIM, g_sn + (size_t)r * DIM, lane);
    }
}

// ---------------------------------------------------------------------------
// B chunk fill (per group): local chunk ci -> s-tile (2*(ci>>3)+gid),
// k-cols [(ci&7)*64, +64). 1024 x 16B segments, 4 per group-thread.
// ---------------------------------------------------------------------------
__device__ __forceinline__ void fill_b_chunk(uint32_t smem_u32,
                                             const __nv_bfloat16* __restrict__ gB,
                                             int ci, int gid, int gtid)
{
    const int st = 2 * (ci >> 3) + gid;
    const int kc = ci & 7;
    const uint32_t bb = A_BYTES
                      + (uint32_t)(gid * NBUF + (ci % NBUF)) * BBUF_BYTES;
#pragma unroll
    for (int i = 0; i < 4; i++) {
        int idx = gtid + i * 256;        // 0..1023
        int r = idx >> 3;                // 8 segs per 128B row
        int s8 = idx & 7;
        const void* src = gB + (size_t)(st * BN + r) * DIM + kc * BK + s8 * 8;
        cp_async16(smem_u32 + bb + swz((uint32_t)(r * 128 + s8 * 16)), src);
    }
    cp_commit();
}

// ---------------------------------------------------------------------------
// GEMM-max: one block per (batch, q-tile), 512 threads = 2 independent
// 256-thread pipelines (own named barrier, own B ring, interleaved s-tiles).
// A resident, shared. Warp tile 64x32 within each group (2m x 4n).
// ---------------------------------------------------------------------------
__global__ __launch_bounds__(NTHREADS, 1) void gemm_max_kernel(float* __restrict__ out)
{
    extern __shared__ char smem[];
    unsigned* rowmaxU = reinterpret_cast<unsigned*>(smem + RM_OFF);
    __shared__ float red[NTHREADS / 32];
    const uint32_t smem_u32 = (uint32_t)__cvta_generic_to_shared(smem);

    const int b   = blockIdx.x >> 4;
    const int qt  = blockIdx.x & 15;
    const int tid = threadIdx.x;
    const int lane = tid & 31;
    const int wid  = tid >> 5;
    const int gid  = wid >> 3;           // warp-group 0 / 1
    const int gtid = tid & 255;
    const int gwid = wid & 7;
    const int wm = (gwid >> 2) * 64;
    const int wn = (gwid & 3) * 32;

    if (tid < BM) rowmaxU[tid] = 0u;

    // ---- A tile: 128 x 512 bf16, 8 swizzled 64-col chunks (all 512 thr) ----
    const __nv_bfloat16* gA = g_qn + (size_t)(b * NQ + qt * BM) * DIM;
#pragma unroll
    for (int i = 0; i < 16; i++) {
        int idx = tid + i * NTHREADS;    // 0..8191 16B segs
        int r = idx >> 6;
        int rest = idx & 63;
        int ch = rest >> 3;
        int s8 = rest & 7;
        const void* src = gA + (size_t)r * DIM + ch * 64 + s8 * 8;
        cp_async16(smem_u32 + ch * 16384 + swz((uint32_t)(r * 128 + s8 * 16)), src);
    }
    cp_commit();

    const __nv_bfloat16* gB = g_sn + (size_t)b * NS * DIM;

    // group prologue: own chunks 0, 1
    fill_b_chunk(smem_u32, gB, 0, gid, gtid);
    fill_b_chunk(smem_u32, gB, 1, gid, gtid);

    // A (and nothing newer than the 2 B groups) must be done before anyone
    // reads A fragments
    cp_wait<2>();
    __syncthreads();

    float C[4][4][4];
#pragma unroll
    for (int mi = 0; mi < 4; mi++)
#pragma unroll
        for (int ni = 0; ni < 4; ni++)
#pragma unroll
            for (int e = 0; e < 4; e++) C[mi][ni][e] = 0.f;

    float rmax[4][2];
#pragma unroll
    for (int mi = 0; mi < 4; mi++) { rmax[mi][0] = -1e30f; rmax[mi][1] = -1e30f; }

    for (int ci = 0; ci < GCHUNK; ci++) {
        if (ci < GCHUNK - 1) cp_wait<1>(); else cp_wait<0>();
        bar_g(1 + gid);
        if (ci + 2 < GCHUNK) fill_b_chunk(smem_u32, gB, ci + 2, gid, gtid);

        const int kc = ci & 7;           // A chunk index for this k-range
        const uint32_t bb = A_BYTES
                          + (uint32_t)(gid * NBUF + (ci % NBUF)) * BBUF_BYTES;

#pragma unroll
        for (int ksp = 0; ksp < 2; ksp++) {
            // B x4 fragments: 2 ksteps per instruction, 4 n-tiles
            unsigned bfr[4][4];
            {
                const uint32_t kb = (uint32_t)(ksp * 64
                                  + ((lane >> 3) & 1) * 16 + (lane >> 4) * 32);
#pragma unroll
                for (int ni = 0; ni < 4; ni++) {
                    int n = wn + ni * 8 + (lane & 7);
                    uint32_t addr = smem_u32 + bb + swz((uint32_t)(n * 128) + kb);
                    asm volatile("ldmatrix.sync.aligned.m8n8.x4.shared.b16 {%0,%1,%2,%3}, [%4];"
                                 : "=r"(bfr[ni][0]), "=r"(bfr[ni][1]),
                                   "=r"(bfr[ni][2]), "=r"(bfr[ni][3])
                                 : "r"(addr));
                }
            }
#pragma unroll
            for (int h = 0; h < 2; h++) {
                const int ks = ksp * 2 + h;
                const uint32_t kb = (uint32_t)(ks * 32 + (lane >> 4) * 16);
                unsigned af[4][4];
#pragma unroll
                for (int mi = 0; mi < 4; mi++) {
                    int r0 = wm + mi * 16 + (lane & 15);
                    uint32_t addr = smem_u32 + kc * 16384
                                  + swz((uint32_t)(r0 * 128) + kb);
                    asm volatile("ldmatrix.sync.aligned.m8n8.x4.shared.b16 {%0,%1,%2,%3}, [%4];"
                                 : "=r"(af[mi][0]), "=r"(af[mi][1]),
                                   "=r"(af[mi][2]), "=r"(af[mi][3])
                                 : "r"(addr));
                }
#pragma unroll
                for (int mi = 0; mi < 4; mi++)
#pragma unroll
                    for (int ni = 0; ni < 4; ni++) {
                        asm volatile(
                            "mma.sync.aligned.m16n8k16.row.col.f32.bf16.bf16.f32 "
                            "{%0,%1,%2,%3}, {%4,%5,%6,%7}, {%8,%9}, {%0,%1,%2,%3};"
                            : "+f"(C[mi][ni][0]), "+f"(C[mi][ni][1]),
                              "+f"(C[mi][ni][2]), "+f"(C[mi][ni][3])
                            : "r"(af[mi][0]), "r"(af[mi][1]),
                              "r"(af[mi][2]), "r"(af[mi][3]),
                              "r"(bfr[ni][2 * h]), "r"(bfr[ni][2 * h + 1]));
                    }
            }
        }

        if (kc == 7) {   // end of s-tile: fold into running row max, reset C
#pragma unroll
            for (int mi = 0; mi < 4; mi++) {
                float m0 = rmax[mi][0], m1 = rmax[mi][1];
#pragma unroll
                for (int ni = 0; ni < 4; ni++) {
                    m0 = fmaxf(m0, fmaxf(C[mi][ni][0], C[mi][ni][1]));
                    m1 = fmaxf(m1, fmaxf(C[mi][ni][2], C[mi][ni][3]));
                    C[mi][ni][0] = 0.f; C[mi][ni][1] = 0.f;
                    C[mi][ni][2] = 0.f; C[mi][ni][3] = 0.f;
                }
                rmax[mi][0] = m0; rmax[mi][1] = m1;
            }
        }
    }

    // epilogue: per-row max across warps/groups via smem atomics
#pragma unroll
    for (int t = 0; t < 4; t++) {
#pragma unroll
        for (int g = 0; g < 2; g++) {
            int row = wm + t * 16 + (lane >> 2) + g * 8;
            atomicMax(&rowmaxU[row], fkey(rmax[t][g]));
        }
    }
    __syncthreads();

    // fused finalize: block sum of (1 - rowmax) -> atomicAdd(out[b], sum/NQ)
    float v = 0.f;
    if (tid < BM) v = 1.0f - funkey(rowmaxU[tid]);
#pragma unroll
    for (int o = 16; o > 0; o >>= 1) v += __shfl_xor_sync(0xFFFFFFFFu, v, o);
    if (lane == 0) red[wid] = v;
    __syncthreads();
    if (wid == 0) {
        float sum = (lane < NTHREADS / 32) ? red[lane] : 0.f;
#pragma unroll
        for (int o = 8; o > 0; o >>= 1) sum += __shfl_xor_sync(0xFFFFFFFFu, sum, o);
        if (lane == 0) atomicAdd(&out[b], sum * (1.0f / NQ));
    }
}

// ---------------------------------------------------------------------------
extern "C" void kernel_launch(void* const* d_in, const int* in_sizes, int n_in,
                              void* d_out, int out_size)
{
    const float* q = (const float*)d_in[0];
    const float* s = (const float*)d_in[1];
    float* out = (float*)d_out;

    cudaFuncSetAttribute(gemm_max_kernel,
                         cudaFuncAttributeMaxDynamicSharedMemorySize, SMEM_TOTAL);

    const int nrows = BATCH * (NQ + NS);
    normalize_all_kernel<<<(nrows + 7) / 8, 256>>>(q, s, out);
    gemm_max_kernel<<<BATCH * (NQ / BM), NTHREADS, SMEM_TOTAL>>>(out);
}